// round 2
// baseline (speedup 1.0000x reference)
#include <cuda_runtime.h>
#include <math.h>

#define N_NODES 8192
#define F_IN 128
#define F_OUT 64
#define NEG_SLOPE 0.2f
#define VERY_SMALL 1000000000000.0f

__device__ float g_s[N_NODES];
__device__ float g_d[N_NODES];

// Kernel A: fused prep + sd.
// Each block redundantly computes ws = w@a_src, wd = w@a_dst (L2-cheap),
// then one warp per row computes s[i] = h[i].ws, d[i] = h[i].wd.
__global__ __launch_bounds__(256) void sd_kernel(const float* __restrict__ h,
                                                 const float* __restrict__ w,
                                                 const float* __restrict__ a) {
    __shared__ float ws[F_IN];
    __shared__ float wd[F_IN];
    const int t = threadIdx.x;

    // threads 0-127 compute ws[k], threads 128-255 compute wd[k]
    {
        int k = t & 127;
        const float* av = a + ((t >= 128) ? F_OUT : 0);
        float acc = 0.f;
        #pragma unroll 8
        for (int j = 0; j < F_OUT; ++j)
            acc += w[k * F_OUT + j] * av[j];
        if (t < 128) ws[k] = acc; else wd[k] = acc;
    }
    __syncthreads();

    // warp per row: 8 rows per block
    const int warp = t >> 5;
    const int lane = t & 31;
    const int i = blockIdx.x * 8 + warp;

    const float4 hv = reinterpret_cast<const float4*>(h + (size_t)i * F_IN)[lane];
    const int k4 = lane * 4;
    float s = hv.x * ws[k4] + hv.y * ws[k4 + 1] + hv.z * ws[k4 + 2] + hv.w * ws[k4 + 3];
    float d = hv.x * wd[k4] + hv.y * wd[k4 + 1] + hv.z * wd[k4 + 2] + hv.w * wd[k4 + 3];
    #pragma unroll
    for (int o = 16; o > 0; o >>= 1) {
        s += __shfl_xor_sync(0xffffffffu, s, o);
        d += __shfl_xor_sync(0xffffffffu, d, o);
    }
    if (lane == 0) { g_s[i] = s; g_d[i] = d; }
}

__device__ __forceinline__ float block_reduce(float v, float* red, bool is_max) {
    __syncthreads();
    #pragma unroll
    for (int o = 16; o > 0; o >>= 1) {
        float other = __shfl_xor_sync(0xffffffffu, v, o);
        v = is_max ? fmaxf(v, other) : (v + other);
    }
    int warp = threadIdx.x >> 5;
    if ((threadIdx.x & 31) == 0) red[warp] = v;
    __syncthreads();
    if (warp == 0) {
        float x = (threadIdx.x < 8) ? red[threadIdx.x] : (is_max ? -INFINITY : 0.f);
        #pragma unroll
        for (int o = 4; o > 0; o >>= 1) {
            float other = __shfl_xor_sync(0xffffffffu, x, o);
            x = is_max ? fmaxf(x, other) : (x + other);
        }
        if (threadIdx.x == 0) red[0] = x;
    }
    __syncthreads();
    return red[0];
}

// Kernel B: one CTA (256 threads) per row. Row values live in REGISTERS
// (8 float4 per thread), no smem stash. adj streamed with evict-first,
// out written streaming; g_d stays hot in L2.
__global__ __launch_bounds__(256) void softmax_kernel(const float* __restrict__ adj,
                                                      float* __restrict__ out) {
    __shared__ float red[8];
    const int i = blockIdx.x;
    const int t = threadIdx.x;
    const float si = g_s[i];

    const float4* ap = reinterpret_cast<const float4*>(adj + (size_t)i * N_NODES);
    const float4* dp = reinterpret_cast<const float4*>(g_d);

    float4 v[8];
    float lmax = -INFINITY;
    #pragma unroll
    for (int k = 0; k < 8; ++k) {
        const int c = t + k * 256;
        float4 av = __ldcs(&ap[c]);   // evict-first: adj read exactly once
        float4 dv = __ldg(&dp[c]);    // reused across all CTAs: keep cached
        float v0 = si + dv.x; v0 = v0 >= 0.f ? v0 : NEG_SLOPE * v0; v0 = (av.x > 0.f) ? v0 : -VERY_SMALL;
        float v1 = si + dv.y; v1 = v1 >= 0.f ? v1 : NEG_SLOPE * v1; v1 = (av.y > 0.f) ? v1 : -VERY_SMALL;
        float v2 = si + dv.z; v2 = v2 >= 0.f ? v2 : NEG_SLOPE * v2; v2 = (av.z > 0.f) ? v2 : -VERY_SMALL;
        float v3 = si + dv.w; v3 = v3 >= 0.f ? v3 : NEG_SLOPE * v3; v3 = (av.w > 0.f) ? v3 : -VERY_SMALL;
        v[k] = make_float4(v0, v1, v2, v3);
        lmax = fmaxf(fmaxf(lmax, v0), fmaxf(v1, fmaxf(v2, v3)));
    }
    const float m = block_reduce(lmax, red, true);

    float lsum = 0.f;
    #pragma unroll
    for (int k = 0; k < 8; ++k) {
        v[k].x = __expf(v[k].x - m);
        v[k].y = __expf(v[k].y - m);
        v[k].z = __expf(v[k].z - m);
        v[k].w = __expf(v[k].w - m);
        lsum += (v[k].x + v[k].y) + (v[k].z + v[k].w);
    }
    const float ssum = block_reduce(lsum, red, false);
    const float inv = 1.0f / ssum;

    float4* op = reinterpret_cast<float4*>(out + (size_t)i * N_NODES);
    #pragma unroll
    for (int k = 0; k < 8; ++k) {
        const int c = t + k * 256;
        float4 o = v[k];
        o.x *= inv; o.y *= inv; o.z *= inv; o.w *= inv;
        __stcs(&op[c], o);   // streaming store: out never re-read
    }
}

extern "C" void kernel_launch(void* const* d_in, const int* in_sizes, int n_in,
                              void* d_out, int out_size) {
    const float* h   = (const float*)d_in[0];  // [8192,128]
    const float* adj = (const float*)d_in[1];  // [8192,8192]
    const float* w   = (const float*)d_in[2];  // [128,64]
    const float* a   = (const float*)d_in[3];  // [128,1]
    float* out = (float*)d_out;

    sd_kernel<<<N_NODES / 8, 256>>>(h, w, a);
    softmax_kernel<<<N_NODES, 256>>>(adj, out);
}

// round 3
// speedup vs baseline: 1.5200x; 1.5200x over previous
#include <cuda_runtime.h>
#include <math.h>

#define N_NODES 8192
#define F_IN 128
#define F_OUT 64
#define NEG_SLOPE 0.2f
#define VERY_SMALL 1000000000000.0f

__device__ float g_s[N_NODES];
__device__ float g_d[N_NODES];

// Kernel A: fused prep + sd. 256 blocks x 256 threads, 32 rows/block.
// Each block stages w into bank-padded smem (coalesced gmem reads,
// conflict-free smem column access), computes ws/wd, then warp-per-row
// dot products for s[i], d[i].
__global__ __launch_bounds__(256) void sd_kernel(const float* __restrict__ h,
                                                 const float* __restrict__ w,
                                                 const float* __restrict__ a) {
    __shared__ float sw[F_IN * 65];        // padded stride 65: bank(k*65+j) = (k+j)%32
    __shared__ float sa[F_IN];
    __shared__ float ws[F_IN];
    __shared__ float wd[F_IN];
    const int t = threadIdx.x;

    if (t < F_IN) sa[t] = a[t];
    // stage w coalesced: 2048 float4, 8 per thread
    const float4* w4 = reinterpret_cast<const float4*>(w);
    #pragma unroll
    for (int r = 0; r < 8; ++r) {
        int f = t + r * 256;                // float4 index
        float4 v = w4[f];
        int k = f >> 4;
        int j = (f & 15) * 4;
        float* dst = &sw[k * 65 + j];
        dst[0] = v.x; dst[1] = v.y; dst[2] = v.z; dst[3] = v.w;
    }
    __syncthreads();

    // threads 0-127: ws[k]; threads 128-255: wd[k]. Conflict-free smem reads.
    {
        int k = t & 127;
        const float* arow = sa + ((t >= 128) ? F_OUT : 0);
        const float* wrow = &sw[k * 65];
        float acc = 0.f;
        #pragma unroll
        for (int j = 0; j < F_OUT; ++j)
            acc += wrow[j] * arow[j];
        if (t < 128) ws[k] = acc; else wd[k] = acc;
    }
    __syncthreads();

    // warp-per-row, 4 rows per warp
    const int warp = t >> 5;
    const int lane = t & 31;
    const int base = blockIdx.x * 32 + warp * 4;
    const float4* ws4 = reinterpret_cast<const float4*>(ws);
    const float4* wd4 = reinterpret_cast<const float4*>(wd);
    const float4 wsv = ws4[lane];
    const float4 wdv = wd4[lane];
    #pragma unroll
    for (int rr = 0; rr < 4; ++rr) {
        const int i = base + rr;
        float4 hv = reinterpret_cast<const float4*>(h + (size_t)i * F_IN)[lane];
        float s = hv.x * wsv.x + hv.y * wsv.y + hv.z * wsv.z + hv.w * wsv.w;
        float d = hv.x * wdv.x + hv.y * wdv.y + hv.z * wdv.z + hv.w * wdv.w;
        #pragma unroll
        for (int o = 16; o > 0; o >>= 1) {
            s += __shfl_xor_sync(0xffffffffu, s, o);
            d += __shfl_xor_sync(0xffffffffu, d, o);
        }
        if (lane == 0) { g_s[i] = s; g_d[i] = d; }
    }
}

__device__ __forceinline__ float block_reduce(float v, float* red, bool is_max) {
    __syncthreads();
    #pragma unroll
    for (int o = 16; o > 0; o >>= 1) {
        float other = __shfl_xor_sync(0xffffffffu, v, o);
        v = is_max ? fmaxf(v, other) : (v + other);
    }
    int warp = threadIdx.x >> 5;
    if ((threadIdx.x & 31) == 0) red[warp] = v;
    __syncthreads();
    if (warp == 0) {
        float x = (threadIdx.x < 16) ? red[threadIdx.x] : (is_max ? -INFINITY : 0.f);
        #pragma unroll
        for (int o = 8; o > 0; o >>= 1) {
            float other = __shfl_xor_sync(0xffffffffu, x, o);
            x = is_max ? fmaxf(x, other) : (x + other);
        }
        if (threadIdx.x == 0) red[0] = x;
    }
    __syncthreads();
    return red[0];
}

// Kernel B: one CTA (512 threads) per row, 4 float4 per thread in registers.
// Lower reg pressure than 256x8 -> more resident warps -> more MLP.
__global__ __launch_bounds__(512) void softmax_kernel(const float* __restrict__ adj,
                                                      float* __restrict__ out) {
    __shared__ float red[16];
    const int i = blockIdx.x;
    const int t = threadIdx.x;
    const float si = g_s[i];

    const float4* ap = reinterpret_cast<const float4*>(adj + (size_t)i * N_NODES);
    const float4* dp = reinterpret_cast<const float4*>(g_d);

    float4 v[4];
    float lmax = -INFINITY;
    #pragma unroll
    for (int k = 0; k < 4; ++k) {
        const int c = t + k * 512;
        float4 av = __ldcs(&ap[c]);   // adj read exactly once: evict-first
        float4 dv = __ldg(&dp[c]);    // reused by all CTAs: keep cached
        float v0 = si + dv.x; v0 = v0 >= 0.f ? v0 : NEG_SLOPE * v0; v0 = (av.x > 0.f) ? v0 : -VERY_SMALL;
        float v1 = si + dv.y; v1 = v1 >= 0.f ? v1 : NEG_SLOPE * v1; v1 = (av.y > 0.f) ? v1 : -VERY_SMALL;
        float v2 = si + dv.z; v2 = v2 >= 0.f ? v2 : NEG_SLOPE * v2; v2 = (av.z > 0.f) ? v2 : -VERY_SMALL;
        float v3 = si + dv.w; v3 = v3 >= 0.f ? v3 : NEG_SLOPE * v3; v3 = (av.w > 0.f) ? v3 : -VERY_SMALL;
        v[k] = make_float4(v0, v1, v2, v3);
        lmax = fmaxf(fmaxf(lmax, v0), fmaxf(v1, fmaxf(v2, v3)));
    }
    const float m = block_reduce(lmax, red, true);

    float lsum = 0.f;
    #pragma unroll
    for (int k = 0; k < 4; ++k) {
        v[k].x = __expf(v[k].x - m);
        v[k].y = __expf(v[k].y - m);
        v[k].z = __expf(v[k].z - m);
        v[k].w = __expf(v[k].w - m);
        lsum += (v[k].x + v[k].y) + (v[k].z + v[k].w);
    }
    const float ssum = block_reduce(lsum, red, false);
    const float inv = 1.0f / ssum;

    float4* op = reinterpret_cast<float4*>(out + (size_t)i * N_NODES);
    #pragma unroll
    for (int k = 0; k < 4; ++k) {
        const int c = t + k * 512;
        float4 o = v[k];
        o.x *= inv; o.y *= inv; o.z *= inv; o.w *= inv;
        __stcs(&op[c], o);   // out never re-read: streaming store
    }
}

extern "C" void kernel_launch(void* const* d_in, const int* in_sizes, int n_in,
                              void* d_out, int out_size) {
    const float* h   = (const float*)d_in[0];  // [8192,128]
    const float* adj = (const float*)d_in[1];  // [8192,8192]
    const float* w   = (const float*)d_in[2];  // [128,64]
    const float* a   = (const float*)d_in[3];  // [128,1]
    float* out = (float*)d_out;

    sd_kernel<<<N_NODES / 32, 256>>>(h, w, a);
    softmax_kernel<<<N_NODES, 512>>>(adj, out);
}

// round 4
// speedup vs baseline: 1.5235x; 1.0023x over previous
#include <cuda_runtime.h>
#include <math.h>

#define N_NODES 8192
#define F_IN 128
#define F_OUT 64
#define NEG_SLOPE 0.2f
#define VERY_SMALL 1000000000000.0f
#define SD_BLOCKS 64
#define ROWS_PER_SD_BLOCK (N_NODES / SD_BLOCKS)   // 128

__device__ float g_s[N_NODES];
__device__ float g_d[N_NODES];
__device__ float g_bmax[SD_BLOCKS];   // per-block max of d

// Kernel A: fused prep + sd + per-block d-max.
// 64 blocks x 256 threads, 128 rows/block (16 rows per warp).
__global__ __launch_bounds__(256) void sd_kernel(const float* __restrict__ h,
                                                 const float* __restrict__ w,
                                                 const float* __restrict__ a) {
    __shared__ float sw[F_IN * 65];   // padded: conflict-free row reads
    __shared__ float sa[F_IN];
    __shared__ float ws[F_IN];
    __shared__ float wd[F_IN];
    __shared__ float wmax[8];
    const int t = threadIdx.x;

    if (t < F_IN) sa[t] = a[t];
    const float4* w4 = reinterpret_cast<const float4*>(w);
    #pragma unroll
    for (int r = 0; r < 8; ++r) {
        int f = t + r * 256;
        float4 v = w4[f];
        int k = f >> 4;
        int j = (f & 15) * 4;
        float* dst = &sw[k * 65 + j];
        dst[0] = v.x; dst[1] = v.y; dst[2] = v.z; dst[3] = v.w;
    }
    __syncthreads();

    {   // threads 0-127: ws[k]; 128-255: wd[k]
        int k = t & 127;
        const float* arow = sa + ((t >= 128) ? F_OUT : 0);
        const float* wrow = &sw[k * 65];
        float acc = 0.f;
        #pragma unroll
        for (int j = 0; j < F_OUT; ++j)
            acc += wrow[j] * arow[j];
        if (t < 128) ws[k] = acc; else wd[k] = acc;
    }
    __syncthreads();

    const int warp = t >> 5;
    const int lane = t & 31;
    const int base = blockIdx.x * ROWS_PER_SD_BLOCK + warp * (ROWS_PER_SD_BLOCK / 8);
    const float4 wsv = reinterpret_cast<const float4*>(ws)[lane];
    const float4 wdv = reinterpret_cast<const float4*>(wd)[lane];

    float dmax = -INFINITY;
    #pragma unroll
    for (int rr = 0; rr < ROWS_PER_SD_BLOCK / 8; ++rr) {
        const int i = base + rr;
        float4 hv = reinterpret_cast<const float4*>(h + (size_t)i * F_IN)[lane];
        float s = hv.x * wsv.x + hv.y * wsv.y + hv.z * wsv.z + hv.w * wsv.w;
        float d = hv.x * wdv.x + hv.y * wdv.y + hv.z * wdv.z + hv.w * wdv.w;
        #pragma unroll
        for (int o = 16; o > 0; o >>= 1) {
            s += __shfl_xor_sync(0xffffffffu, s, o);
            d += __shfl_xor_sync(0xffffffffu, d, o);
        }
        if (lane == 0) { g_s[i] = s; g_d[i] = d; dmax = fmaxf(dmax, d); }
    }
    if (lane == 0) wmax[warp] = dmax;
    __syncthreads();
    if (t == 0) {
        float m = wmax[0];
        #pragma unroll
        for (int k = 1; k < 8; ++k) m = fmaxf(m, wmax[k]);
        g_bmax[blockIdx.x] = m;
    }
}

__device__ __forceinline__ float block_reduce_sum(float v, float* red) {
    #pragma unroll
    for (int o = 16; o > 0; o >>= 1)
        v += __shfl_xor_sync(0xffffffffu, v, o);
    int warp = threadIdx.x >> 5;
    if ((threadIdx.x & 31) == 0) red[warp] = v;
    __syncthreads();
    if (warp == 0) {
        float x = (threadIdx.x < 8) ? red[threadIdx.x] : 0.f;
        #pragma unroll
        for (int o = 4; o > 0; o >>= 1)
            x += __shfl_xor_sync(0xffffffffu, x, o);
        if (threadIdx.x == 0) red[0] = x;
    }
    __syncthreads();
    return red[0];
}

// Kernel B: one CTA (256 threads) per row, 8 float4 in registers.
// No max pass: stabilizer M_i = lrelu(s_i + max_j d_j) is a provable upper
// bound (lrelu monotone, global d-max >= masked d-max), softmax exact for
// any M with no overflow. One fused load+exp+sum pass, ONE block reduce.
__global__ __launch_bounds__(256) void softmax_kernel(const float* __restrict__ adj,
                                                      float* __restrict__ out) {
    __shared__ float red[8];
    const int i = blockIdx.x;
    const int t = threadIdx.x;
    const float si = g_s[i];

    // Fold per-block d-maxes (64 scalars, L1-hot broadcast) -> D, no barrier.
    float D = -INFINITY;
    #pragma unroll
    for (int b = 0; b < SD_BLOCKS; ++b) D = fmaxf(D, __ldg(&g_bmax[b]));
    float M = si + D;
    M = M >= 0.f ? M : NEG_SLOPE * M;

    const float4* ap = reinterpret_cast<const float4*>(adj + (size_t)i * N_NODES);
    const float4* dp = reinterpret_cast<const float4*>(g_d);

    float4 p[8];
    float lsum = 0.f;
    #pragma unroll
    for (int k = 0; k < 8; ++k) {
        const int c = t + k * 256;
        float4 av = __ldcs(&ap[c]);   // adj read once: evict-first
        float4 dv = __ldg(&dp[c]);    // reused by all CTAs: keep cached
        float v0 = si + dv.x; v0 = v0 >= 0.f ? v0 : NEG_SLOPE * v0; v0 = (av.x > 0.f) ? v0 : -VERY_SMALL;
        float v1 = si + dv.y; v1 = v1 >= 0.f ? v1 : NEG_SLOPE * v1; v1 = (av.y > 0.f) ? v1 : -VERY_SMALL;
        float v2 = si + dv.z; v2 = v2 >= 0.f ? v2 : NEG_SLOPE * v2; v2 = (av.z > 0.f) ? v2 : -VERY_SMALL;
        float v3 = si + dv.w; v3 = v3 >= 0.f ? v3 : NEG_SLOPE * v3; v3 = (av.w > 0.f) ? v3 : -VERY_SMALL;
        p[k].x = __expf(v0 - M);
        p[k].y = __expf(v1 - M);
        p[k].z = __expf(v2 - M);
        p[k].w = __expf(v3 - M);
        lsum += (p[k].x + p[k].y) + (p[k].z + p[k].w);
    }
    const float ssum = block_reduce_sum(lsum, red);
    const float inv = 1.0f / ssum;

    float4* op = reinterpret_cast<float4*>(out + (size_t)i * N_NODES);
    #pragma unroll
    for (int k = 0; k < 8; ++k) {
        const int c = t + k * 256;
        float4 o = p[k];
        o.x *= inv; o.y *= inv; o.z *= inv; o.w *= inv;
        __stcs(&op[c], o);   // out never re-read: streaming store
    }
}

extern "C" void kernel_launch(void* const* d_in, const int* in_sizes, int n_in,
                              void* d_out, int out_size) {
    const float* h   = (const float*)d_in[0];  // [8192,128]
    const float* adj = (const float*)d_in[1];  // [8192,8192]
    const float* w   = (const float*)d_in[2];  // [128,64]
    const float* a   = (const float*)d_in[3];  // [128,1]
    float* out = (float*)d_out;

    sd_kernel<<<SD_BLOCKS, 256>>>(h, w, a);
    softmax_kernel<<<N_NODES, 256>>>(adj, out);
}